// round 8
// baseline (speedup 1.0000x reference)
#include <cuda_runtime.h>
#include <cstdint>

// RWKV v4 single-token forward, persistent kernel, round 8.
// Key insight: previous kernels were capped at ~2.3TB/s by the per-SM LDG
// issue floor (~1.82 cyc/LDG * 16B = 8.8 B/cyc/SM). This round streams ALL
// GEMV weights via cp.async.bulk (TMA, bypasses LSU; LTS-cap ~6300 B/cyc
// chip-wide) into double-buffered smem tiles; warps consume via LDS.
// Next-stage tiles are issued before each grid barrier so TMA overlaps
// barrier + elementwise dead time.

#define E    1024
#define HH   4096
#define NL   24
#define NV   50277
#define T    1024
#define WPB  32
#define TILE_R 8
#define TILE_F (TILE_R * E)

// ---- persistent device scratch ----
__device__ float g_kvr[3 * E];
__device__ float g_ow[E];
__device__ float g_fk[HH];
__device__ float g_fr[E];
__device__ __align__(16) float g_fvd[4 * E];   // [row*4 + c] quarter partials
__device__ unsigned int g_bar[2];              // memset per launch

struct P {
    const float *ctx, *state, *ln0w, *ln0b, *ln1w, *ln1b, *ln2w, *ln2b;
    const float *td, *tf, *tmk, *tmv, *tmr, *kw, *vw, *rw, *ow;
    const float *ftmk, *ftmr, *fkw, *frw, *fvw, *lnoutw, *lnoutb, *head;
    float* out;
    int nb;
    int ws;
};

__device__ __forceinline__ void grid_sync(int nb) {
    __syncthreads();
    if (threadIdx.x == 0) {
        unsigned int gen = ((volatile unsigned int*)g_bar)[1];
        __threadfence();
        if (atomicAdd(&g_bar[0], 1u) == (unsigned int)(nb - 1)) {
            atomicExch(&g_bar[0], 0u);
            __threadfence();
            atomicAdd(&g_bar[1], 1u);
        } else {
            while (((volatile unsigned int*)g_bar)[1] == gen) { __nanosleep(64); }
        }
        __threadfence();
    }
    __syncthreads();
}

__device__ __forceinline__ void block_reduce2(float& a, float& b, float* sr) {
    #pragma unroll
    for (int o = 16; o; o >>= 1) {
        a += __shfl_down_sync(0xFFFFFFFFu, a, o);
        b += __shfl_down_sync(0xFFFFFFFFu, b, o);
    }
    int w = threadIdx.x >> 5, l = threadIdx.x & 31;
    __syncthreads();
    if (l == 0) { sr[w] = a; sr[w + WPB] = b; }
    __syncthreads();
    if (threadIdx.x == 0) {
        float sa = 0.f, sb2 = 0.f;
        #pragma unroll
        for (int i = 0; i < WPB; i++) { sa += sr[i]; sb2 += sr[i + WPB]; }
        sr[2 * WPB] = sa; sr[2 * WPB + 1] = sb2;
    }
    __syncthreads();
    a = sr[2 * WPB];
    b = sr[2 * WPB + 1];
}

// ---- mbarrier / bulk-copy primitives ----
__device__ __forceinline__ void mb_init(uint32_t a, uint32_t cnt) {
    asm volatile("mbarrier.init.shared.b64 [%0], %1;" :: "r"(a), "r"(cnt) : "memory");
}
__device__ __forceinline__ void mb_expect(uint32_t a, uint32_t tx) {
    asm volatile("mbarrier.arrive.expect_tx.shared.b64 _, [%0], %1;" :: "r"(a), "r"(tx) : "memory");
}
__device__ __forceinline__ void mb_wait(uint32_t a, uint32_t parity) {
    uint32_t done;
    asm volatile(
        "{\n\t.reg .pred p;\n\t"
        "mbarrier.try_wait.parity.acquire.cta.shared::cta.b64 p, [%1], %2;\n\t"
        "selp.b32 %0, 1, 0, p;\n\t}"
        : "=r"(done) : "r"(a), "r"(parity) : "memory");
    if (!done) {
        asm volatile(
            "{\n\t.reg .pred P1;\n\t"
            "WAIT_LOOP_%=:\n\t"
            "mbarrier.try_wait.parity.acquire.cta.shared::cta.b64 P1, [%0], %1, 0x989680;\n\t"
            "@P1 bra.uni WAIT_DONE_%=;\n\t"
            "bra.uni WAIT_LOOP_%=;\n\t"
            "WAIT_DONE_%=:\n\t}"
            :: "r"(a), "r"(parity) : "memory");
    }
}
__device__ __forceinline__ void bulk_ld(uint32_t dst, const float* src, uint32_t bytes, uint32_t mbar) {
    asm volatile(
        "cp.async.bulk.shared::cluster.global.mbarrier::complete_tx::bytes [%0], [%1], %2, [%3];"
        :: "r"(dst), "l"(src), "r"(bytes), "r"(mbar) : "memory");
}

// ---- virtual-row mapping (all stages: 4KB contiguous chunks) ----
__device__ __forceinline__ const float* srcptr(const P& p, int stg, int l, int vr) {
    switch (stg) {
        case 0: { int m = vr >> 10;
                  const float* W = (m == 0 ? p.kw : (m == 1 ? p.vw : p.rw)) + (size_t)l * E * E;
                  return W + (size_t)(vr & 1023) * E; }
        case 1: return p.ow + (size_t)l * E * E + (size_t)vr * E;
        case 2: return (vr < 4096) ? p.fkw + (size_t)l * HH * E + (size_t)vr * E
                                   : p.frw + (size_t)l * E * E + (size_t)(vr - 4096) * E;
        case 3: return p.fvw + (size_t)l * E * HH + (size_t)vr * E;
        default: return p.head + (size_t)vr * E;
    }
}
__device__ __forceinline__ int capf(int stg, int vr) {
    if (stg == 0) return 1024 - (vr & 1023);
    if (stg == 2) return (vr < 4096) ? (4096 - vr) : (5120 - vr);
    return 1 << 30;
}
__device__ __forceinline__ int xoff(int stg, int vr) {
    switch (stg) {
        case 0: return (vr >> 10) << 10;
        case 2: return (vr < 4096) ? 0 : E;
        case 3: return (vr & 3) << 10;
        default: return 0;
    }
}
__device__ __forceinline__ float* outp(const P& p, int stg, int vr) {
    switch (stg) {
        case 0: return g_kvr + vr;
        case 1: return g_ow + vr;
        case 2: return (vr < 4096) ? g_fk + vr : g_fr + (vr - 4096);
        case 3: return g_fvd + vr;
        default: return p.out + vr;
    }
}

struct Pipe { int icur, iend, stg, l; int ivr[2], inr[2]; };

__device__ __forceinline__ void pipe_issue(Pipe& q, int buf, const P& p,
                                           uint32_t tiles_u32, uint32_t mb) {
    if (q.icur >= q.iend) { q.inr[buf] = 0; return; }
    int nr = q.iend - q.icur;
    int c = capf(q.stg, q.icur);
    if (nr > TILE_R) nr = TILE_R;
    if (nr > c) nr = c;
    q.ivr[buf] = q.icur; q.inr[buf] = nr;
    if (threadIdx.x == 0) {
        uint32_t bytes = (uint32_t)nr * E * 4u;
        mb_expect(mb + buf * 8, bytes);
        bulk_ld(tiles_u32 + buf * TILE_F * 4, srcptr(p, q.stg, q.l, q.icur), bytes, mb + buf * 8);
    }
    q.icur += nr;
}

__device__ __forceinline__ void pipe_begin(Pipe& q, int stg, int l, int NVR, const P& p,
                                           uint32_t tiles_u32, uint32_t mb) {
    q.stg = stg; q.l = l;
    q.icur = (int)(((long long)NVR * blockIdx.x) / p.nb);
    q.iend = (int)(((long long)NVR * (blockIdx.x + 1)) / p.nb);
    pipe_issue(q, 0, p, tiles_u32, mb);
    pipe_issue(q, 1, p, tiles_u32, mb);
}

__device__ __forceinline__ void pipe_drain(Pipe& q, const P& p, float* tiles_f, float* sop,
                                           float (*spart)[32], uint32_t tiles_u32,
                                           uint32_t mb, int* ph) {
    int cbuf = 0;
    const int tid = threadIdx.x, lane = tid & 31, w = tid >> 5;
    while (q.inr[cbuf] > 0) {
        mb_wait(mb + cbuf * 8, (uint32_t)ph[cbuf]); ph[cbuf] ^= 1;
        int nr = q.inr[cbuf], tvr = q.ivr[cbuf];
        int r = w >> 2, qd = w & 3;
        if (r < nr) {
            const float4* wv = (const float4*)(tiles_f + cbuf * TILE_F + r * E + qd * 256);
            const float4* xv = (const float4*)(sop + xoff(q.stg, tvr + r) + qd * 256);
            float4 w0 = wv[lane],      x0 = xv[lane];
            float4 w1 = wv[lane + 32], x1 = xv[lane + 32];
            float acc = w0.x * x0.x + w0.y * x0.y + w0.z * x0.z + w0.w * x0.w
                      + w1.x * x1.x + w1.y * x1.y + w1.z * x1.z + w1.w * x1.w;
            #pragma unroll
            for (int o = 16; o; o >>= 1) acc += __shfl_down_sync(0xFFFFFFFFu, acc, o);
            if (lane == 0) spart[cbuf][w] = acc;
        }
        __syncthreads();
        pipe_issue(q, cbuf, p, tiles_u32, mb);
        if (tid < nr) {
            float4 v = ((const float4*)spart[cbuf])[tid];
            *outp(p, q.stg, tvr + tid) = v.x + v.y + v.z + v.w;
        }
        cbuf ^= 1;
    }
}

#define SMEM_FLOATS (E + HH + 2 * TILE_F)

__global__ void __launch_bounds__(T, 1) rwkv_kernel(P p) {
    extern __shared__ float smem[];
    float* sx      = smem;             // [E]
    float* sop     = smem + E;         // [HH]
    float* tiles_f = smem + E + HH;    // [2 * TILE_F]
    __shared__ float sred[2 * WPB + 2];
    __shared__ __align__(16) float spart[2][32];
    __shared__ __align__(8) uint64_t mbars[2];

    const int tid = threadIdx.x;
    const bool w0 = (p.ws && blockIdx.x == 0);
    float* outS = p.out + NV;

    uint32_t mb, tiles_u32;
    asm("{ .reg .u64 t; cvta.to.shared.u64 t, %1; cvt.u32.u64 %0, t; }"
        : "=r"(mb) : "l"((void*)&mbars[0]));
    asm("{ .reg .u64 t; cvta.to.shared.u64 t, %1; cvt.u32.u64 %0, t; }"
        : "=r"(tiles_u32) : "l"((void*)tiles_f));

    if (tid == 0) { mb_init(mb, 1); mb_init(mb + 8, 1); }
    __syncthreads();

    Pipe q;
    int ph[2] = {0, 0};

    // issue layer-0 kvr tiles; LN0 runs under the TMA
    pipe_begin(q, 0, 0, 3 * E, p, tiles_u32, mb);

    float s = 0.f, s2 = 0.f;
    for (int i = tid; i < E; i += T) { float v = __ldg(p.ctx + i); sx[i] = v; s += v; s2 += v * v; }
    block_reduce2(s, s2, sred);
    {
        float mu = s * (1.f / E);
        float rs = rsqrtf(s2 * (1.f / E) - mu * mu + 1e-5f);
        for (int i = tid; i < E; i += T)
            sx[i] = (sx[i] - mu) * rs * __ldg(p.ln0w + i) + __ldg(p.ln0b + i);
    }
    __syncthreads();

    for (int l = 0; l < NL; l++) {
        const float* st = p.state + (size_t)l * 5 * E;

        // ---- elementwise A: combine prev FFN + LN1 + time-mix ----
        if (l > 0) {
            for (int i = tid; i < E; i += T) {
                float4 fv4 = *(const float4*)(g_fvd + 4 * i);
                float fr = 1.f / (1.f + __expf(-g_fr[i]));
                sx[i] += fr * ((fv4.x + fv4.y) + (fv4.z + fv4.w));
            }
        }
        s = 0.f; s2 = 0.f;
        for (int i = tid; i < E; i += T) { float v = sx[i]; s += v; s2 += v * v; }
        block_reduce2(s, s2, sred);
        {
            float mu = s * (1.f / E);
            float rs = rsqrtf(s2 * (1.f / E) - mu * mu + 1e-5f);
            for (int i = tid; i < E; i += T) {
                float xn = (sx[i] - mu) * rs * __ldg(p.ln1w + l * E + i) + __ldg(p.ln1b + l * E + i);
                float spv = __ldg(st + E + i);
                float a = __ldg(p.tmk + l * E + i), b = __ldg(p.tmv + l * E + i), c = __ldg(p.tmr + l * E + i);
                sop[i]         = xn * a + spv * (1.f - a);
                sop[E + i]     = xn * b + spv * (1.f - b);
                sop[2 * E + i] = xn * c + spv * (1.f - c);
                if (w0) outS[(size_t)(5 * l + 1) * E + i] = xn;
            }
        }
        __syncthreads();
        pipe_drain(q, p, tiles_f, sop, spart, tiles_u32, mb, ph);   // -> g_kvr
        pipe_begin(q, 1, l, E, p, tiles_u32, mb);                   // issue ow
        grid_sync(p.nb);

        // ---- elementwise B: WKV ----
        for (int i = tid; i < E; i += T) {
            float k  = g_kvr[i];
            float v  = g_kvr[E + i];
            float rr = g_kvr[2 * E + i];
            float A = __ldg(st + 2 * E + i), B = __ldg(st + 3 * E + i), Pp = __ldg(st + 4 * E + i);
            float ww = __ldg(p.tf + l * E + i) + k;
            float qq = fmaxf(Pp, ww);
            float e1 = __expf(Pp - qq), e2 = __expf(ww - qq);
            float num = e1 * A + e2 * v, den = e1 * B + e2;
            float r = 1.f / (1.f + __expf(-rr));
            sop[i] = r * num / den;
            if (w0) {
                float ww2 = Pp + __ldg(p.td + l * E + i);
                float p2 = fmaxf(ww2, k);
                float e1b = __expf(ww2 - p2), e2b = __expf(k - p2);
                outS[(size_t)(5 * l + 2) * E + i] = e1b * A + e2b * v;
                outS[(size_t)(5 * l + 3) * E + i] = e1b * B + e2b;
                outS[(size_t)(5 * l + 4) * E + i] = p2;
            }
        }
        __syncthreads();
        pipe_drain(q, p, tiles_f, sop, spart, tiles_u32, mb, ph);   // -> g_ow
        pipe_begin(q, 2, l, HH + E, p, tiles_u32, mb);              // issue fk+fr
        grid_sync(p.nb);

        // ---- elementwise C: x += ow; LN2 + chan-mix ----
        for (int i = tid; i < E; i += T) sx[i] += g_ow[i];
        s = 0.f; s2 = 0.f;
        for (int i = tid; i < E; i += T) { float v = sx[i]; s += v; s2 += v * v; }
        block_reduce2(s, s2, sred);
        {
            float mu = s * (1.f / E);
            float rs = rsqrtf(s2 * (1.f / E) - mu * mu + 1e-5f);
            for (int i = tid; i < E; i += T) {
                float xn2 = (sx[i] - mu) * rs * __ldg(p.ln2w + l * E + i) + __ldg(p.ln2b + l * E + i);
                float sv = __ldg(st + i);
                float a = __ldg(p.ftmk + l * E + i), b = __ldg(p.ftmr + l * E + i);
                sop[i]     = xn2 * a + sv * (1.f - a);
                sop[E + i] = xn2 * b + sv * (1.f - b);
                if (w0) outS[(size_t)(5 * l + 0) * E + i] = xn2;
            }
        }
        __syncthreads();
        pipe_drain(q, p, tiles_f, sop, spart, tiles_u32, mb, ph);   // -> g_fk, g_fr
        pipe_begin(q, 3, l, 4 * E, p, tiles_u32, mb);               // issue fv
        grid_sync(p.nb);

        // ---- elementwise D: kk = relu^2(fk) ----
        for (int i = tid; i < HH; i += T) {
            float a = fmaxf(g_fk[i], 0.f);
            sop[i] = a * a;
        }
        __syncthreads();
        pipe_drain(q, p, tiles_f, sop, spart, tiles_u32, mb, ph);   // -> g_fvd
        if (l + 1 < NL) pipe_begin(q, 0, l + 1, 3 * E, p, tiles_u32, mb);
        else            pipe_begin(q, 4, 0, NV, p, tiles_u32, mb);  // issue head
        grid_sync(p.nb);
    }

    // ---- final: combine last FFN, LN_out, head GEMV ----
    for (int i = tid; i < E; i += T) {
        float4 fv4 = *(const float4*)(g_fvd + 4 * i);
        float fr = 1.f / (1.f + __expf(-g_fr[i]));
        sx[i] += fr * ((fv4.x + fv4.y) + (fv4.z + fv4.w));
    }
    s = 0.f; s2 = 0.f;
    for (int i = tid; i < E; i += T) { float v = sx[i]; s += v; s2 += v * v; }
    block_reduce2(s, s2, sred);
    {
        float mu = s * (1.f / E);
        float rs = rsqrtf(s2 * (1.f / E) - mu * mu + 1e-5f);
        for (int i = tid; i < E; i += T)
            sop[i] = (sx[i] - mu) * rs * __ldg(p.lnoutw + i) + __ldg(p.lnoutb + i);
    }
    __syncthreads();
    pipe_drain(q, p, tiles_f, sop, spart, tiles_u32, mb, ph);       // -> p.out[0..NV)
}

extern "C" void kernel_launch(void* const* d_in, const int* in_sizes, int n_in,
                              void* d_out, int out_size) {
    (void)in_sizes; (void)n_in;
    P p;
    p.ctx    = (const float*)d_in[0];
    p.state  = (const float*)d_in[1];
    p.ln0w   = (const float*)d_in[2];
    p.ln0b   = (const float*)d_in[3];
    p.ln1w   = (const float*)d_in[4];
    p.ln1b   = (const float*)d_in[5];
    p.ln2w   = (const float*)d_in[6];
    p.ln2b   = (const float*)d_in[7];
    p.td     = (const float*)d_in[8];
    p.tf     = (const float*)d_in[9];
    p.tmk    = (const float*)d_in[10];
    p.tmv    = (const float*)d_in[11];
    p.tmr    = (const float*)d_in[12];
    p.kw     = (const float*)d_in[13];
    p.vw     = (const float*)d_in[14];
    p.rw     = (const float*)d_in[15];
    p.ow     = (const float*)d_in[16];
    p.ftmk   = (const float*)d_in[17];
    p.ftmr   = (const float*)d_in[18];
    p.fkw    = (const float*)d_in[19];
    p.frw    = (const float*)d_in[20];
    p.fvw    = (const float*)d_in[21];
    p.lnoutw = (const float*)d_in[22];
    p.lnoutb = (const float*)d_in[23];
    p.head   = (const float*)d_in[24];
    p.out    = (float*)d_out;

    int dev = 0;
    cudaGetDevice(&dev);
    int nsm = 0;
    cudaDeviceGetAttribute(&nsm, cudaDevAttrMultiProcessorCount, dev);
    if (nsm <= 0) nsm = 148;
    if (nsm > 256) nsm = 256;
    p.nb = nsm;
    p.ws = (out_size >= NV + 5 * NL * E) ? 1 : 0;

    cudaFuncSetAttribute(rwkv_kernel, cudaFuncAttributeMaxDynamicSharedMemorySize,
                         SMEM_FLOATS * sizeof(float));

    void* baddr = nullptr;
    cudaGetSymbolAddress(&baddr, g_bar);
    cudaMemsetAsync(baddr, 0, sizeof(unsigned int) * 2, 0);

    rwkv_kernel<<<nsm, T, SMEM_FLOATS * sizeof(float)>>>(p);
}